// round 4
// baseline (speedup 1.0000x reference)
#include <cuda_runtime.h>

#define NN   100000
#define F1   128
#define F2   64
#define KDIM 128
#define EMAX 1700000

// ---------------- scratch (device globals; no allocation allowed) ----------------
__device__ int   g_is64;                  // 1 if edge_index is int64
__device__ int   g_src[EMAX];
__device__ int   g_dst[EMAX];
__device__ float g_w[EMAX];               // per-edge norm weight
__device__ float g_deg[NN];
__device__ float g_dinv[NN];
__device__ float g_h1[(size_t)NN * F1];   // layer-1 pre-aggregation features
__device__ float g_out1[(size_t)NN * F1]; // layer-1 aggregated output (pre-relu)
__device__ float g_h2[(size_t)NN * F2];   // layer-2 pre-aggregation features

// ---------------- edge-index dtype sniff + convert ----------------
// Sample ONLY odd word indices < nelem: in-bounds whether the buffer is
// int32 (nelem words) or int64 (2*nelem words). For int64 little-endian data
// with ids < 2^31 those words are element high-halves -> all zero. For int32
// data they are node ids -> essentially never all zero.
__global__ void detect_dtype(const unsigned int* __restrict__ raw, int nelem, int* flag) {
    if (threadIdx.x == 0 && blockIdx.x == 0) {
        int half = nelem >> 1;                 // number of odd words we may probe
        int step = half / 64; if (step < 1) step = 1;
        unsigned int acc = 0;
        for (int i = 0; i < 64; i++) {
            int k = (int)(((long long)i * step) % half);
            acc |= raw[2 * k + 1];             // word index < nelem: always in bounds
        }
        *flag = (acc == 0) ? 1 : 0;
    }
}

__global__ void convert_edges(const void* __restrict__ raw, int E,
                              const int* __restrict__ flag,
                              int* __restrict__ src, int* __restrict__ dst) {
    int e = blockIdx.x * blockDim.x + threadIdx.x;
    if (e >= E) return;
    if (*flag) {
        const long long* p = (const long long*)raw;
        src[e] = (int)p[e];
        dst[e] = (int)p[(size_t)E + e];
    } else {
        const int* p = (const int*)raw;
        src[e] = p[e];
        dst[e] = p[E + e];
    }
}

// ---------------- degree / normalization ----------------
__global__ void deg_init(float* __restrict__ deg, int n) {
    int i = blockIdx.x * blockDim.x + threadIdx.x;
    if (i < n) deg[i] = 1.0f;  // self-loop
}

__global__ void deg_count(const int* __restrict__ dst, float* __restrict__ deg, int E) {
    int e = blockIdx.x * blockDim.x + threadIdx.x;
    if (e < E) atomicAdd(&deg[dst[e]], 1.0f);  // exact: integer counts < 2^24
}

__global__ void dinv_k(const float* __restrict__ deg, float* __restrict__ dinv, int n) {
    int i = blockIdx.x * blockDim.x + threadIdx.x;
    if (i < n) dinv[i] = rsqrtf(deg[i]);
}

__global__ void edge_w(const int* __restrict__ src, const int* __restrict__ dst,
                       const float* __restrict__ dinv, float* __restrict__ w, int E) {
    int e = blockIdx.x * blockDim.x + threadIdx.x;
    if (e < E) w[e] = __ldg(dinv + src[e]) * __ldg(dinv + dst[e]);
}

// ---------------- GEMM: C = A @ B, dual epilogue ----------------
// Stores H[row][col] = acc  and  OUT[row][col] = acc * dinv[row]^2 + bias[col]
// (OUT pre-seeded with self-loop contribution + bias; scatter accumulates on top)
// BM=64, BN=64, BK=16, 256 threads, 4x4 microtile per thread.
template <bool RELU_IN>
__global__ __launch_bounds__(256)
void gemm_dual(const float* __restrict__ A, const float* __restrict__ B,
               float* __restrict__ H, float* __restrict__ OUT,
               const float* __restrict__ dinv, const float* __restrict__ bias,
               int N, int K, int F)
{
    __shared__ __align__(16) float As[16][64];
    __shared__ __align__(16) float Bs[16][68];

    const int t   = threadIdx.x;
    const int bm0 = blockIdx.x * 64;
    const int bn0 = blockIdx.y * 64;

    const int ar = t >> 2;          // 0..63 (A tile row)
    const int ak = (t & 3) * 4;     // 0,4,8,12 (A tile k, float4)
    const int br = t >> 4;          // 0..15 (B tile k-row)
    const int bc = (t & 15) * 4;    // 0..60 (B tile col, float4)
    const int ty = t >> 4;          // 0..15
    const int tx = t & 15;          // 0..15

    const int  arow    = bm0 + ar;
    const bool arow_ok = arow < N;

    float acc[4][4] = {};

    for (int k0 = 0; k0 < K; k0 += 16) {
        float4 av = make_float4(0.f, 0.f, 0.f, 0.f);
        if (arow_ok) {
            av = *reinterpret_cast<const float4*>(A + (size_t)arow * K + k0 + ak);
            if (RELU_IN) {
                av.x = fmaxf(av.x, 0.f); av.y = fmaxf(av.y, 0.f);
                av.z = fmaxf(av.z, 0.f); av.w = fmaxf(av.w, 0.f);
            }
        }
        float4 bv = *reinterpret_cast<const float4*>(B + (size_t)(k0 + br) * F + bn0 + bc);

        __syncthreads();  // protect previous tile's compute
        As[ak + 0][ar] = av.x;
        As[ak + 1][ar] = av.y;
        As[ak + 2][ar] = av.z;
        As[ak + 3][ar] = av.w;
        *reinterpret_cast<float4*>(&Bs[br][bc]) = bv;
        __syncthreads();

        #pragma unroll
        for (int kk = 0; kk < 16; kk++) {
            float4 a = *reinterpret_cast<const float4*>(&As[kk][ty * 4]);
            float4 b = *reinterpret_cast<const float4*>(&Bs[kk][tx * 4]);
            acc[0][0] += a.x * b.x; acc[0][1] += a.x * b.y; acc[0][2] += a.x * b.z; acc[0][3] += a.x * b.w;
            acc[1][0] += a.y * b.x; acc[1][1] += a.y * b.y; acc[1][2] += a.y * b.z; acc[1][3] += a.y * b.w;
            acc[2][0] += a.z * b.x; acc[2][1] += a.z * b.y; acc[2][2] += a.z * b.z; acc[2][3] += a.z * b.w;
            acc[3][0] += a.w * b.x; acc[3][1] += a.w * b.y; acc[3][2] += a.w * b.z; acc[3][3] += a.w * b.w;
        }
    }

    float4 bvv = *reinterpret_cast<const float4*>(bias + bn0 + tx * 4);
    #pragma unroll
    for (int i = 0; i < 4; i++) {
        int row = bm0 + ty * 4 + i;
        if (row >= N) continue;
        float di = dinv[row];
        float d2 = di * di;
        size_t base = (size_t)row * F + bn0 + tx * 4;
        float4 h = make_float4(acc[i][0], acc[i][1], acc[i][2], acc[i][3]);
        *reinterpret_cast<float4*>(H + base) = h;
        float4 o = make_float4(h.x * d2 + bvv.x, h.y * d2 + bvv.y,
                               h.z * d2 + bvv.z, h.w * d2 + bvv.w);
        *reinterpret_cast<float4*>(OUT + base) = o;
    }
}

// ---------------- edge scatter: OUT[dst] += H[src] * w[e] ----------------
// LOGG: log2(threads per edge); each thread handles one float4 of features.
template <int LOGG>
__global__ __launch_bounds__(256)
void scatter_edges(const int* __restrict__ src, const int* __restrict__ dst,
                   const float* __restrict__ w, int E,
                   const float* __restrict__ H, float* __restrict__ OUT)
{
    const int G = 1 << LOGG;      // threads per edge
    const int F = G * 4;          // features
    long long idx = (long long)blockIdx.x * blockDim.x + threadIdx.x;
    long long total = (long long)E << LOGG;
    if (idx >= total) return;

    int e = (int)(idx >> LOGG);
    int c = (int)(idx & (G - 1));

    int   s  = __ldg(src + e);
    int   d  = __ldg(dst + e);
    float we = __ldg(w + e);

    float4 v = __ldg(reinterpret_cast<const float4*>(H + (size_t)s * F) + c);
    float* p = OUT + (size_t)d * F + (size_t)c * 4;
    asm volatile("red.global.add.v4.f32 [%0], {%1,%2,%3,%4};"
                 :: "l"(p), "f"(v.x * we), "f"(v.y * we), "f"(v.z * we), "f"(v.w * we)
                 : "memory");
}

// ---------------- final relu (in-place, float4) ----------------
__global__ void relu4(float4* __restrict__ x, int n4) {
    int i = blockIdx.x * blockDim.x + threadIdx.x;
    if (i < n4) {
        float4 v = x[i];
        v.x = fmaxf(v.x, 0.f); v.y = fmaxf(v.y, 0.f);
        v.z = fmaxf(v.z, 0.f); v.w = fmaxf(v.w, 0.f);
        x[i] = v;
    }
}

// ---------------- launch ----------------
extern "C" void kernel_launch(void* const* d_in, const int* in_sizes, int n_in,
                              void* d_out, int out_size)
{
    const float* x   = (const float*)d_in[0];
    const void*  ei  = d_in[1];                 // int32 or int64, sniffed on device
    const float* W1  = (const float*)d_in[2];
    const float* b1  = (const float*)d_in[3];
    const float* W2  = (const float*)d_in[4];
    const float* b2  = (const float*)d_in[5];
    float*       out = (float*)d_out;

    const int E = in_sizes[1] / 2;

    int *is64, *src, *dst;
    float *w, *deg, *dinv, *h1, *out1, *h2;
    cudaGetSymbolAddress((void**)&is64, g_is64);
    cudaGetSymbolAddress((void**)&src,  g_src);
    cudaGetSymbolAddress((void**)&dst,  g_dst);
    cudaGetSymbolAddress((void**)&w,    g_w);
    cudaGetSymbolAddress((void**)&deg,  g_deg);
    cudaGetSymbolAddress((void**)&dinv, g_dinv);
    cudaGetSymbolAddress((void**)&h1,   g_h1);
    cudaGetSymbolAddress((void**)&out1, g_out1);
    cudaGetSymbolAddress((void**)&h2,   g_h2);

    // 0) canonicalize edge index to int32
    detect_dtype<<<1, 32>>>((const unsigned int*)ei, in_sizes[1], is64);
    convert_edges<<<(E + 255) / 256, 256>>>(ei, E, is64, src, dst);

    // 1) normalization coefficients
    deg_init<<<(NN + 255) / 256, 256>>>(deg, NN);
    deg_count<<<(E + 255) / 256, 256>>>(dst, deg, E);
    dinv_k<<<(NN + 255) / 256, 256>>>(deg, dinv, NN);
    edge_w<<<(E + 255) / 256, 256>>>(src, dst, dinv, w, E);

    // 2) layer 1: GEMM (+ self-loop & bias epilogue), then edge scatter
    dim3 g1((NN + 63) / 64, F1 / 64);
    gemm_dual<false><<<g1, 256>>>(x, W1, h1, out1, dinv, b1, NN, KDIM, F1);

    long long tot1 = (long long)E << 5;  // E * 32 threads
    scatter_edges<5><<<(unsigned)((tot1 + 255) / 256), 256>>>(src, dst, w, E, h1, out1);

    // 3) layer 2: GEMM with fused ReLU on input (+ self-loop & bias epilogue into d_out)
    dim3 g2((NN + 63) / 64, F2 / 64);
    gemm_dual<true><<<g2, 256>>>(out1, W2, h2, out, dinv, b2, NN, KDIM, F2);

    long long tot2 = (long long)E << 4;  // E * 16 threads
    scatter_edges<4><<<(unsigned)((tot2 + 255) / 256), 256>>>(src, dst, w, E, h2, out);

    // 4) final relu in place on d_out
    relu4<<<(NN * F2 / 4 + 255) / 256, 256>>>((float4*)out, NN * F2 / 4);
}

// round 5
// speedup vs baseline: 1.3476x; 1.3476x over previous
#include <cuda_runtime.h>

#define NN   100000
#define F1   128
#define F2   64
#define KDIM 128
#define EMAX 1700000

// ---------------- scratch (device globals; no allocation allowed) ----------------
__device__ int   g_is64;
__device__ int   g_src[EMAX];
__device__ int   g_dst[EMAX];
__device__ int   g_hist[NN];               // in-degree (excl self-loop)
__device__ int   g_offs[NN + 1];           // CSR offsets by dst
__device__ int   g_cursor[NN];             // fill cursors
__device__ int   g_blocksum[128];
__device__ int   g_csrc[EMAX];             // CSR: src per slot
__device__ float g_cw[EMAX];               // CSR: edge weight per slot
__device__ float g_dinv[NN];
__device__ float g_h1[(size_t)NN * F1];
__device__ float g_out1[(size_t)NN * F1];
__device__ float g_h2[(size_t)NN * F2];

// ---------------- edge-index dtype sniff ----------------
__global__ void detect_dtype(const unsigned int* __restrict__ raw, int nelem, int* flag) {
    if (threadIdx.x == 0 && blockIdx.x == 0) {
        int half = nelem >> 1;
        int step = half / 64; if (step < 1) step = 1;
        unsigned int acc = 0;
        for (int i = 0; i < 64; i++) {
            int k = (int)(((long long)i * step) % half);
            acc |= raw[2 * k + 1];          // word index < nelem: in bounds either way
        }
        *flag = (acc == 0) ? 1 : 0;
    }
}

__global__ void zero_hist(int* __restrict__ h, int n) {
    int i = blockIdx.x * blockDim.x + threadIdx.x;
    if (i < n) h[i] = 0;
}

// convert to int32 + build dst histogram in one pass
__global__ void convert_hist(const void* __restrict__ raw, int E,
                             const int* __restrict__ flag,
                             int* __restrict__ src, int* __restrict__ dst,
                             int* __restrict__ hist) {
    int e = blockIdx.x * blockDim.x + threadIdx.x;
    if (e >= E) return;
    int s, d;
    if (*flag) {
        const long long* p = (const long long*)raw;
        s = (int)p[e]; d = (int)p[(size_t)E + e];
    } else {
        const int* p = (const int*)raw;
        s = p[e]; d = p[E + e];
    }
    src[e] = s; dst[e] = d;
    atomicAdd(&hist[d], 1);
}

__global__ void dinv_k(const int* __restrict__ hist, float* __restrict__ dinv, int n) {
    int i = blockIdx.x * blockDim.x + threadIdx.x;
    if (i < n) dinv[i] = rsqrtf(1.0f + (float)hist[i]);  // +1 self-loop
}

// ---------------- exclusive scan over NN bins (1024 elems / block) ----------------
__global__ void scan_reduce(const int* __restrict__ hist, int* __restrict__ bsum, int n) {
    __shared__ int sh[256];
    int base = blockIdx.x * 1024, t = threadIdx.x;
    int s = 0;
    #pragma unroll
    for (int j = 0; j < 4; j++) {
        int idx = base + t * 4 + j;
        s += (idx < n) ? hist[idx] : 0;
    }
    sh[t] = s; __syncthreads();
    for (int off = 128; off > 0; off >>= 1) {
        if (t < off) sh[t] += sh[t + off];
        __syncthreads();
    }
    if (t == 0) bsum[blockIdx.x] = sh[0];
}

__global__ void scan_bsums(int* __restrict__ bsum, int nb) {
    __shared__ int sh[128];
    int t = threadIdx.x;
    int own = (t < nb) ? bsum[t] : 0;
    sh[t] = own; __syncthreads();
    for (int off = 1; off < 128; off <<= 1) {
        int y = (t >= off) ? sh[t - off] : 0;
        __syncthreads();
        sh[t] += y;
        __syncthreads();
    }
    if (t < nb) bsum[t] = sh[t] - own;   // exclusive
}

__global__ void scan_final(const int* __restrict__ hist, const int* __restrict__ bbase,
                           int* __restrict__ offs, int* __restrict__ cursor, int n) {
    __shared__ int sh[256];
    int base = blockIdx.x * 1024, t = threadIdx.x;
    int i0 = base + t * 4;
    int v[4], s = 0;
    #pragma unroll
    for (int j = 0; j < 4; j++) {
        int idx = i0 + j;
        v[j] = (idx < n) ? hist[idx] : 0;
        s += v[j];
    }
    sh[t] = s; __syncthreads();
    for (int off = 1; off < 256; off <<= 1) {
        int y = (t >= off) ? sh[t - off] : 0;
        __syncthreads();
        sh[t] += y;
        __syncthreads();
    }
    int run = bbase[blockIdx.x] + sh[t] - s;   // exclusive prefix of this chunk
    #pragma unroll
    for (int j = 0; j < 4; j++) {
        int idx = i0 + j;
        if (idx < n) { offs[idx] = run; cursor[idx] = run; run += v[j]; }
    }
}

__global__ void set_last(int* __restrict__ offs, int n, int E) {
    if (threadIdx.x == 0) offs[n] = E;
}

// ---------------- CSR fill (counting sort by dst) ----------------
__global__ void fill_csr(const int* __restrict__ src, const int* __restrict__ dst,
                         const float* __restrict__ dinv, int* __restrict__ cursor,
                         int* __restrict__ csrc, float* __restrict__ cw, int E) {
    int e = blockIdx.x * blockDim.x + threadIdx.x;
    if (e >= E) return;
    int s = src[e], d = dst[e];
    int pos = atomicAdd(&cursor[d], 1);
    csrc[pos] = s;
    cw[pos]   = __ldg(dinv + s) * __ldg(dinv + d);
}

// ---------------- GEMM: C = A @ B, dual epilogue ----------------
// BM=128, BN=64, BK=16, 128 threads, 8x8 microtile (LDS/FMA balanced).
// H = A@B ; OUT = (A@B)*dinv[row]^2 + bias  (self-loop + bias pre-seed)
template <bool RELU_IN>
__global__ __launch_bounds__(128)
void gemm_dual(const float* __restrict__ A, const float* __restrict__ B,
               float* __restrict__ H, float* __restrict__ OUT,
               const float* __restrict__ dinv, const float* __restrict__ bias,
               int N, int K, int F)
{
    __shared__ __align__(16) float As[16][132];
    __shared__ __align__(16) float Bs[16][68];

    const int t   = threadIdx.x;
    const int bm0 = blockIdx.x * 128;
    const int bn0 = blockIdx.y * 64;

    const int ty = t >> 3;   // 0..15
    const int tx = t & 7;    // 0..7
    const int brow = t >> 3; // B tile k-row 0..15
    const int bcol = (t & 7) * 8;

    const int  arow    = bm0 + t;      // each thread loads A row t
    const bool arow_ok = arow < N;

    float acc[8][8] = {};

    for (int k0 = 0; k0 < K; k0 += 16) {
        float4 av[4];
        #pragma unroll
        for (int j = 0; j < 4; j++) {
            if (arow_ok) {
                av[j] = *reinterpret_cast<const float4*>(A + (size_t)arow * K + k0 + j * 4);
                if (RELU_IN) {
                    av[j].x = fmaxf(av[j].x, 0.f); av[j].y = fmaxf(av[j].y, 0.f);
                    av[j].z = fmaxf(av[j].z, 0.f); av[j].w = fmaxf(av[j].w, 0.f);
                }
            } else {
                av[j] = make_float4(0.f, 0.f, 0.f, 0.f);
            }
        }
        float4 bv0 = *reinterpret_cast<const float4*>(B + (size_t)(k0 + brow) * F + bn0 + bcol);
        float4 bv1 = *reinterpret_cast<const float4*>(B + (size_t)(k0 + brow) * F + bn0 + bcol + 4);

        __syncthreads();
        #pragma unroll
        for (int j = 0; j < 4; j++) {
            As[j * 4 + 0][t] = av[j].x;
            As[j * 4 + 1][t] = av[j].y;
            As[j * 4 + 2][t] = av[j].z;
            As[j * 4 + 3][t] = av[j].w;
        }
        *reinterpret_cast<float4*>(&Bs[brow][bcol])     = bv0;
        *reinterpret_cast<float4*>(&Bs[brow][bcol + 4]) = bv1;
        __syncthreads();

        #pragma unroll
        for (int kk = 0; kk < 16; kk++) {
            float4 a0 = *reinterpret_cast<const float4*>(&As[kk][ty * 8]);
            float4 a1 = *reinterpret_cast<const float4*>(&As[kk][ty * 8 + 4]);
            float4 b0 = *reinterpret_cast<const float4*>(&Bs[kk][tx * 8]);
            float4 b1 = *reinterpret_cast<const float4*>(&Bs[kk][tx * 8 + 4]);
            float a[8] = {a0.x, a0.y, a0.z, a0.w, a1.x, a1.y, a1.z, a1.w};
            float b[8] = {b0.x, b0.y, b0.z, b0.w, b1.x, b1.y, b1.z, b1.w};
            #pragma unroll
            for (int i = 0; i < 8; i++)
                #pragma unroll
                for (int j = 0; j < 8; j++)
                    acc[i][j] += a[i] * b[j];
        }
    }

    float4 bb0 = *reinterpret_cast<const float4*>(bias + bn0 + tx * 8);
    float4 bb1 = *reinterpret_cast<const float4*>(bias + bn0 + tx * 8 + 4);
    const float bbv[8] = {bb0.x, bb0.y, bb0.z, bb0.w, bb1.x, bb1.y, bb1.z, bb1.w};

    #pragma unroll
    for (int i = 0; i < 8; i++) {
        int row = bm0 + ty * 8 + i;
        if (row >= N) continue;
        float di = dinv[row];
        float d2 = di * di;
        size_t base = (size_t)row * F + bn0 + tx * 8;
        float4 h0 = make_float4(acc[i][0], acc[i][1], acc[i][2], acc[i][3]);
        float4 h1v = make_float4(acc[i][4], acc[i][5], acc[i][6], acc[i][7]);
        *reinterpret_cast<float4*>(H + base)     = h0;
        *reinterpret_cast<float4*>(H + base + 4) = h1v;
        float4 o0 = make_float4(h0.x * d2 + bbv[0], h0.y * d2 + bbv[1],
                                h0.z * d2 + bbv[2], h0.w * d2 + bbv[3]);
        float4 o1 = make_float4(h1v.x * d2 + bbv[4], h1v.y * d2 + bbv[5],
                                h1v.z * d2 + bbv[6], h1v.w * d2 + bbv[7]);
        *reinterpret_cast<float4*>(OUT + base)     = o0;
        *reinterpret_cast<float4*>(OUT + base + 4) = o1;
    }
}

// ---------------- CSR aggregation: OUT[n] += sum_e w[e] * H[src[e]] ----------------
// Warp per node, F=128: lane owns float4. No atomics.
__global__ __launch_bounds__(256)
void aggregate128(const int* __restrict__ offs, const int* __restrict__ csrc,
                  const float* __restrict__ cw, const float* __restrict__ H,
                  float* __restrict__ OUT, int n)
{
    int warp = (blockIdx.x * blockDim.x + threadIdx.x) >> 5;
    int lane = threadIdx.x & 31;
    if (warp >= n) return;
    int beg = __ldg(offs + warp), end = __ldg(offs + warp + 1);

    float4* op = reinterpret_cast<float4*>(OUT + (size_t)warp * 128) + lane;
    float4 acc = *op;

    int j = beg;
    for (; j + 1 < end; j += 2) {
        int   s0 = __ldg(csrc + j);     float w0 = __ldg(cw + j);
        int   s1 = __ldg(csrc + j + 1); float w1 = __ldg(cw + j + 1);
        float4 v0 = __ldg(reinterpret_cast<const float4*>(H + (size_t)s0 * 128) + lane);
        float4 v1 = __ldg(reinterpret_cast<const float4*>(H + (size_t)s1 * 128) + lane);
        acc.x += v0.x * w0 + v1.x * w1;
        acc.y += v0.y * w0 + v1.y * w1;
        acc.z += v0.z * w0 + v1.z * w1;
        acc.w += v0.w * w0 + v1.w * w1;
    }
    if (j < end) {
        int s = __ldg(csrc + j); float w = __ldg(cw + j);
        float4 v = __ldg(reinterpret_cast<const float4*>(H + (size_t)s * 128) + lane);
        acc.x += v.x * w; acc.y += v.y * w; acc.z += v.z * w; acc.w += v.w * w;
    }
    *op = acc;
}

// Warp per node, F=64: lane owns float2.
__global__ __launch_bounds__(256)
void aggregate64(const int* __restrict__ offs, const int* __restrict__ csrc,
                 const float* __restrict__ cw, const float* __restrict__ H,
                 float* __restrict__ OUT, int n)
{
    int warp = (blockIdx.x * blockDim.x + threadIdx.x) >> 5;
    int lane = threadIdx.x & 31;
    if (warp >= n) return;
    int beg = __ldg(offs + warp), end = __ldg(offs + warp + 1);

    float2* op = reinterpret_cast<float2*>(OUT + (size_t)warp * 64) + lane;
    float2 acc = *op;

    int j = beg;
    for (; j + 1 < end; j += 2) {
        int   s0 = __ldg(csrc + j);     float w0 = __ldg(cw + j);
        int   s1 = __ldg(csrc + j + 1); float w1 = __ldg(cw + j + 1);
        float2 v0 = __ldg(reinterpret_cast<const float2*>(H + (size_t)s0 * 64) + lane);
        float2 v1 = __ldg(reinterpret_cast<const float2*>(H + (size_t)s1 * 64) + lane);
        acc.x += v0.x * w0 + v1.x * w1;
        acc.y += v0.y * w0 + v1.y * w1;
    }
    if (j < end) {
        int s = __ldg(csrc + j); float w = __ldg(cw + j);
        float2 v = __ldg(reinterpret_cast<const float2*>(H + (size_t)s * 64) + lane);
        acc.x += v.x * w; acc.y += v.y * w;
    }
    *op = acc;
}

// ---------------- final relu ----------------
__global__ void relu4(float4* __restrict__ x, int n4) {
    int i = blockIdx.x * blockDim.x + threadIdx.x;
    if (i < n4) {
        float4 v = x[i];
        v.x = fmaxf(v.x, 0.f); v.y = fmaxf(v.y, 0.f);
        v.z = fmaxf(v.z, 0.f); v.w = fmaxf(v.w, 0.f);
        x[i] = v;
    }
}

// ---------------- launch ----------------
extern "C" void kernel_launch(void* const* d_in, const int* in_sizes, int n_in,
                              void* d_out, int out_size)
{
    const float* x   = (const float*)d_in[0];
    const void*  ei  = d_in[1];
    const float* W1  = (const float*)d_in[2];
    const float* b1  = (const float*)d_in[3];
    const float* W2  = (const float*)d_in[4];
    const float* b2  = (const float*)d_in[5];
    float*       out = (float*)d_out;

    const int E  = in_sizes[1] / 2;
    const int NB = (NN + 1023) / 1024;

    int *is64, *src, *dst, *hist, *offs, *cursor, *bsum, *csrc;
    float *cw, *dinv, *h1, *out1, *h2;
    cudaGetSymbolAddress((void**)&is64,   g_is64);
    cudaGetSymbolAddress((void**)&src,    g_src);
    cudaGetSymbolAddress((void**)&dst,    g_dst);
    cudaGetSymbolAddress((void**)&hist,   g_hist);
    cudaGetSymbolAddress((void**)&offs,   g_offs);
    cudaGetSymbolAddress((void**)&cursor, g_cursor);
    cudaGetSymbolAddress((void**)&bsum,   g_blocksum);
    cudaGetSymbolAddress((void**)&csrc,   g_csrc);
    cudaGetSymbolAddress((void**)&cw,     g_cw);
    cudaGetSymbolAddress((void**)&dinv,   g_dinv);
    cudaGetSymbolAddress((void**)&h1,     g_h1);
    cudaGetSymbolAddress((void**)&out1,   g_out1);
    cudaGetSymbolAddress((void**)&h2,     g_h2);

    // 0) canonicalize edges, histogram by dst
    zero_hist<<<(NN + 255) / 256, 256>>>(hist, NN);
    detect_dtype<<<1, 32>>>((const unsigned int*)ei, in_sizes[1], is64);
    convert_hist<<<(E + 255) / 256, 256>>>(ei, E, is64, src, dst, hist);

    // 1) normalization + CSR offsets
    dinv_k<<<(NN + 255) / 256, 256>>>(hist, dinv, NN);
    scan_reduce<<<NB, 256>>>(hist, bsum, NN);
    scan_bsums<<<1, 128>>>(bsum, NB);
    scan_final<<<NB, 256>>>(hist, bsum, offs, cursor, NN);
    set_last<<<1, 1>>>(offs, NN, E);
    fill_csr<<<(E + 255) / 256, 256>>>(src, dst, dinv, cursor, csrc, cw, E);

    // 2) layer 1
    dim3 g1((NN + 127) / 128, F1 / 64);
    gemm_dual<false><<<g1, 128>>>(x, W1, h1, out1, dinv, b1, NN, KDIM, F1);
    aggregate128<<<(NN * 32 + 255) / 256, 256>>>(offs, csrc, cw, h1, out1, NN);

    // 3) layer 2 (fused ReLU on input; epilogue writes d_out pre-seed)
    dim3 g2((NN + 127) / 128, F2 / 64);
    gemm_dual<true><<<g2, 128>>>(out1, W2, h2, out, dinv, b2, NN, KDIM, F2);
    aggregate64<<<(NN * 32 + 255) / 256, 256>>>(offs, csrc, cw, h2, out, NN);

    // 4) final relu
    relu4<<<(NN * F2 / 4 + 255) / 256, 256>>>((float4*)out, NN * F2 / 4);
}

// round 6
// speedup vs baseline: 1.4825x; 1.1001x over previous
#include <cuda_runtime.h>
#include <cuda_fp16.h>

#define NN   100000
#define F1   128
#define F2   64
#define KDIM 128
#define EMAX 1700000

// ---------------- scratch (device globals; no allocation allowed) ----------------
__device__ int    g_is64;
__device__ int    g_hist[NN];               // in-degree (excl self-loop)
__device__ int    g_offs[NN + 1];           // CSR offsets by dst
__device__ int    g_cursor[NN];             // fill cursors
__device__ int    g_blocksum[128];
__device__ int    g_csrc[EMAX];             // CSR: src per slot
__device__ float  g_cw[EMAX];               // CSR: edge weight per slot
__device__ float  g_dinv[NN];
__device__ __half g_h1[(size_t)NN * F1];    // layer-1 features, fp16 (gather operand)
__device__ float  g_out1[(size_t)NN * F1];  // layer-1 aggregated output (fp32)
__device__ __half g_h2[(size_t)NN * F2];    // layer-2 features, fp16 (gather operand)

// ---------------- edge-index dtype sniff ----------------
__global__ void detect_dtype(const unsigned int* __restrict__ raw, int nelem, int* flag) {
    if (threadIdx.x == 0 && blockIdx.x == 0) {
        int half = nelem >> 1;
        int step = half / 64; if (step < 1) step = 1;
        unsigned int acc = 0;
        for (int i = 0; i < 64; i++) {
            int k = (int)(((long long)i * step) % half);
            acc |= raw[2 * k + 1];          // word index < nelem: in bounds either way
        }
        *flag = (acc == 0) ? 1 : 0;
    }
}

__global__ void zero_hist(int* __restrict__ h, int n) {
    int i = blockIdx.x * blockDim.x + threadIdx.x;
    if (i < n) h[i] = 0;
}

// dst histogram straight from the raw edge buffer
__global__ void hist_k(const void* __restrict__ raw, int E,
                       const int* __restrict__ flag, int* __restrict__ hist) {
    int e = blockIdx.x * blockDim.x + threadIdx.x;
    if (e >= E) return;
    int d;
    if (*flag) d = (int)((const long long*)raw)[(size_t)E + e];
    else       d = ((const int*)raw)[E + e];
    atomicAdd(&hist[d], 1);
}

__global__ void dinv_k(const int* __restrict__ hist, float* __restrict__ dinv, int n) {
    int i = blockIdx.x * blockDim.x + threadIdx.x;
    if (i < n) dinv[i] = rsqrtf(1.0f + (float)hist[i]);  // +1 self-loop
}

// ---------------- exclusive scan over NN bins (1024 elems / block) ----------------
__global__ void scan_reduce(const int* __restrict__ hist, int* __restrict__ bsum, int n) {
    __shared__ int sh[256];
    int base = blockIdx.x * 1024, t = threadIdx.x;
    int s = 0;
    #pragma unroll
    for (int j = 0; j < 4; j++) {
        int idx = base + t * 4 + j;
        s += (idx < n) ? hist[idx] : 0;
    }
    sh[t] = s; __syncthreads();
    for (int off = 128; off > 0; off >>= 1) {
        if (t < off) sh[t] += sh[t + off];
        __syncthreads();
    }
    if (t == 0) bsum[blockIdx.x] = sh[0];
}

__global__ void scan_bsums(int* __restrict__ bsum, int nb) {
    __shared__ int sh[128];
    int t = threadIdx.x;
    int own = (t < nb) ? bsum[t] : 0;
    sh[t] = own; __syncthreads();
    for (int off = 1; off < 128; off <<= 1) {
        int y = (t >= off) ? sh[t - off] : 0;
        __syncthreads();
        sh[t] += y;
        __syncthreads();
    }
    if (t < nb) bsum[t] = sh[t] - own;   // exclusive
}

__global__ void scan_final(const int* __restrict__ hist, const int* __restrict__ bbase,
                           int* __restrict__ offs, int* __restrict__ cursor, int n) {
    __shared__ int sh[256];
    int base = blockIdx.x * 1024, t = threadIdx.x;
    int i0 = base + t * 4;
    int v[4], s = 0;
    #pragma unroll
    for (int j = 0; j < 4; j++) {
        int idx = i0 + j;
        v[j] = (idx < n) ? hist[idx] : 0;
        s += v[j];
    }
    sh[t] = s; __syncthreads();
    for (int off = 1; off < 256; off <<= 1) {
        int y = (t >= off) ? sh[t - off] : 0;
        __syncthreads();
        sh[t] += y;
        __syncthreads();
    }
    int run = bbase[blockIdx.x] + sh[t] - s;   // exclusive prefix of this chunk
    #pragma unroll
    for (int j = 0; j < 4; j++) {
        int idx = i0 + j;
        if (idx < n) { offs[idx] = run; cursor[idx] = run; run += v[j]; }
    }
}

__global__ void set_last(int* __restrict__ offs, int n, int E) {
    if (threadIdx.x == 0) offs[n] = E;
}

// ---------------- CSR fill (counting sort by dst), straight from raw ----------------
__global__ void fill_csr(const void* __restrict__ raw, int E,
                         const int* __restrict__ flag,
                         const float* __restrict__ dinv, int* __restrict__ cursor,
                         int* __restrict__ csrc, float* __restrict__ cw) {
    int e = blockIdx.x * blockDim.x + threadIdx.x;
    if (e >= E) return;
    int s, d;
    if (*flag) {
        const long long* p = (const long long*)raw;
        s = (int)p[e]; d = (int)p[(size_t)E + e];
    } else {
        const int* p = (const int*)raw;
        s = p[e]; d = p[E + e];
    }
    int pos = atomicAdd(&cursor[d], 1);
    csrc[pos] = s;
    cw[pos]   = __ldg(dinv + s) * __ldg(dinv + d);
}

// ---------------- GEMM: C = A @ B, dual epilogue ----------------
// BM=128, BN=64, BK=16, 128 threads, 8x8 microtile.
// H(fp16) = A@B ; OUT(fp32) = (A@B)*dinv[row]^2 + bias  (self-loop + bias pre-seed)
template <bool RELU_IN>
__global__ __launch_bounds__(128)
void gemm_dual(const float* __restrict__ A, const float* __restrict__ B,
               __half* __restrict__ H, float* __restrict__ OUT,
               const float* __restrict__ dinv, const float* __restrict__ bias,
               int N, int K, int F)
{
    __shared__ __align__(16) float As[16][132];
    __shared__ __align__(16) float Bs[16][68];

    const int t   = threadIdx.x;
    const int bm0 = blockIdx.x * 128;
    const int bn0 = blockIdx.y * 64;

    const int ty = t >> 3;   // 0..15
    const int tx = t & 7;    // 0..7
    const int brow = t >> 3; // B tile k-row 0..15
    const int bcol = (t & 7) * 8;

    const int  arow    = bm0 + t;      // each thread loads A row t
    const bool arow_ok = arow < N;

    float acc[8][8] = {};

    for (int k0 = 0; k0 < K; k0 += 16) {
        float4 av[4];
        #pragma unroll
        for (int j = 0; j < 4; j++) {
            if (arow_ok) {
                av[j] = *reinterpret_cast<const float4*>(A + (size_t)arow * K + k0 + j * 4);
                if (RELU_IN) {
                    av[j].x = fmaxf(av[j].x, 0.f); av[j].y = fmaxf(av[j].y, 0.f);
                    av[j].z = fmaxf(av[j].z, 0.f); av[j].w = fmaxf(av[j].w, 0.f);
                }
            } else {
                av[j] = make_float4(0.f, 0.f, 0.f, 0.f);
            }
        }
        float4 bv0 = *reinterpret_cast<const float4*>(B + (size_t)(k0 + brow) * F + bn0 + bcol);
        float4 bv1 = *reinterpret_cast<const float4*>(B + (size_t)(k0 + brow) * F + bn0 + bcol + 4);

        __syncthreads();
        #pragma unroll
        for (int j = 0; j < 4; j++) {
            As[j * 4 + 0][t] = av[j].x;
            As[j * 4 + 1][t] = av[j].y;
            As[j * 4 + 2][t] = av[j].z;
            As[j * 4 + 3][t] = av[j].w;
        }
        *reinterpret_cast<float4*>(&Bs[brow][bcol])     = bv0;
        *reinterpret_cast<float4*>(&Bs[brow][bcol + 4]) = bv1;
        __syncthreads();

        #pragma unroll
        for (int kk = 0; kk < 16; kk++) {
            float4 a0 = *reinterpret_cast<const float4*>(&As[kk][ty * 8]);
            float4 a1 = *reinterpret_cast<const float4*>(&As[kk][ty * 8 + 4]);
            float4 b0 = *reinterpret_cast<const float4*>(&Bs[kk][tx * 8]);
            float4 b1 = *reinterpret_cast<const float4*>(&Bs[kk][tx * 8 + 4]);
            float a[8] = {a0.x, a0.y, a0.z, a0.w, a1.x, a1.y, a1.z, a1.w};
            float b[8] = {b0.x, b0.y, b0.z, b0.w, b1.x, b1.y, b1.z, b1.w};
            #pragma unroll
            for (int i = 0; i < 8; i++)
                #pragma unroll
                for (int j = 0; j < 8; j++)
                    acc[i][j] += a[i] * b[j];
        }
    }

    float4 bb0 = *reinterpret_cast<const float4*>(bias + bn0 + tx * 8);
    float4 bb1 = *reinterpret_cast<const float4*>(bias + bn0 + tx * 8 + 4);
    const float bbv[8] = {bb0.x, bb0.y, bb0.z, bb0.w, bb1.x, bb1.y, bb1.z, bb1.w};

    #pragma unroll
    for (int i = 0; i < 8; i++) {
        int row = bm0 + ty * 8 + i;
        if (row >= N) continue;
        float di = dinv[row];
        float d2 = di * di;
        size_t base = (size_t)row * F + bn0 + tx * 8;

        // fp16 store of h (message operand)
        __half2 hh[4];
        hh[0] = __float22half2_rn(make_float2(acc[i][0], acc[i][1]));
        hh[1] = __float22half2_rn(make_float2(acc[i][2], acc[i][3]));
        hh[2] = __float22half2_rn(make_float2(acc[i][4], acc[i][5]));
        hh[3] = __float22half2_rn(make_float2(acc[i][6], acc[i][7]));
        *reinterpret_cast<uint4*>(H + base) = *reinterpret_cast<const uint4*>(hh);

        // fp32 pre-seed: self-loop + bias (exact)
        float4 o0 = make_float4(acc[i][0] * d2 + bbv[0], acc[i][1] * d2 + bbv[1],
                                acc[i][2] * d2 + bbv[2], acc[i][3] * d2 + bbv[3]);
        float4 o1 = make_float4(acc[i][4] * d2 + bbv[4], acc[i][5] * d2 + bbv[5],
                                acc[i][6] * d2 + bbv[6], acc[i][7] * d2 + bbv[7]);
        *reinterpret_cast<float4*>(OUT + base)     = o0;
        *reinterpret_cast<float4*>(OUT + base + 4) = o1;
    }
}

// ---------------- CSR aggregation (fp16 gather, fp32 accumulate) ----------------
// Warp per node, F=128: lane owns 4 halves (uint2).
__global__ __launch_bounds__(256)
void aggregate128(const int* __restrict__ offs, const int* __restrict__ csrc,
                  const float* __restrict__ cw, const __half* __restrict__ H,
                  float* __restrict__ OUT, int n)
{
    int warp = (blockIdx.x * blockDim.x + threadIdx.x) >> 5;
    int lane = threadIdx.x & 31;
    if (warp >= n) return;
    int beg = __ldg(offs + warp), end = __ldg(offs + warp + 1);

    const uint2* Hv = reinterpret_cast<const uint2*>(H);   // 32 x uint2 per row
    float4* op = reinterpret_cast<float4*>(OUT + (size_t)warp * 128) + lane;
    float4 acc = *op;

    int j = beg;
    for (; j + 1 < end; j += 2) {
        int   s0 = __ldg(csrc + j);     float w0 = __ldg(cw + j);
        int   s1 = __ldg(csrc + j + 1); float w1 = __ldg(cw + j + 1);
        uint2 u0 = __ldg(Hv + (size_t)s0 * 32 + lane);
        uint2 u1 = __ldg(Hv + (size_t)s1 * 32 + lane);
        float2 a0 = __half22float2(*reinterpret_cast<const __half2*>(&u0.x));
        float2 b0 = __half22float2(*reinterpret_cast<const __half2*>(&u0.y));
        float2 a1 = __half22float2(*reinterpret_cast<const __half2*>(&u1.x));
        float2 b1 = __half22float2(*reinterpret_cast<const __half2*>(&u1.y));
        acc.x += a0.x * w0 + a1.x * w1;
        acc.y += a0.y * w0 + a1.y * w1;
        acc.z += b0.x * w0 + b1.x * w1;
        acc.w += b0.y * w0 + b1.y * w1;
    }
    if (j < end) {
        int s = __ldg(csrc + j); float w = __ldg(cw + j);
        uint2 u = __ldg(Hv + (size_t)s * 32 + lane);
        float2 a = __half22float2(*reinterpret_cast<const __half2*>(&u.x));
        float2 b = __half22float2(*reinterpret_cast<const __half2*>(&u.y));
        acc.x += a.x * w; acc.y += a.y * w; acc.z += b.x * w; acc.w += b.y * w;
    }
    *op = acc;
}

// Warp per node, F=64: lane owns 2 halves (one half2). ReLU fused at store.
__global__ __launch_bounds__(256)
void aggregate64_relu(const int* __restrict__ offs, const int* __restrict__ csrc,
                      const float* __restrict__ cw, const __half* __restrict__ H,
                      float* __restrict__ OUT, int n)
{
    int warp = (blockIdx.x * blockDim.x + threadIdx.x) >> 5;
    int lane = threadIdx.x & 31;
    if (warp >= n) return;
    int beg = __ldg(offs + warp), end = __ldg(offs + warp + 1);

    const unsigned int* Hv = reinterpret_cast<const unsigned int*>(H); // 32 x half2 per row
    float2* op = reinterpret_cast<float2*>(OUT + (size_t)warp * 64) + lane;
    float2 acc = *op;

    int j = beg;
    for (; j + 1 < end; j += 2) {
        int   s0 = __ldg(csrc + j);     float w0 = __ldg(cw + j);
        int   s1 = __ldg(csrc + j + 1); float w1 = __ldg(cw + j + 1);
        unsigned int u0 = __ldg(Hv + (size_t)s0 * 32 + lane);
        unsigned int u1 = __ldg(Hv + (size_t)s1 * 32 + lane);
        float2 v0 = __half22float2(*reinterpret_cast<const __half2*>(&u0));
        float2 v1 = __half22float2(*reinterpret_cast<const __half2*>(&u1));
        acc.x += v0.x * w0 + v1.x * w1;
        acc.y += v0.y * w0 + v1.y * w1;
    }
    if (j < end) {
        int s = __ldg(csrc + j); float w = __ldg(cw + j);
        unsigned int u = __ldg(Hv + (size_t)s * 32 + lane);
        float2 v = __half22float2(*reinterpret_cast<const __half2*>(&u));
        acc.x += v.x * w; acc.y += v.y * w;
    }
    acc.x = fmaxf(acc.x, 0.f);
    acc.y = fmaxf(acc.y, 0.f);
    *op = acc;
}

// ---------------- launch ----------------
extern "C" void kernel_launch(void* const* d_in, const int* in_sizes, int n_in,
                              void* d_out, int out_size)
{
    const float* x   = (const float*)d_in[0];
    const void*  ei  = d_in[1];
    const float* W1  = (const float*)d_in[2];
    const float* b1  = (const float*)d_in[3];
    const float* W2  = (const float*)d_in[4];
    const float* b2  = (const float*)d_in[5];
    float*       out = (float*)d_out;

    const int E  = in_sizes[1] / 2;
    const int NB = (NN + 1023) / 1024;

    int *is64, *hist, *offs, *cursor, *bsum, *csrc;
    float *cw, *dinv, *out1;
    __half *h1, *h2;
    cudaGetSymbolAddress((void**)&is64,   g_is64);
    cudaGetSymbolAddress((void**)&hist,   g_hist);
    cudaGetSymbolAddress((void**)&offs,   g_offs);
    cudaGetSymbolAddress((void**)&cursor, g_cursor);
    cudaGetSymbolAddress((void**)&bsum,   g_blocksum);
    cudaGetSymbolAddress((void**)&csrc,   g_csrc);
    cudaGetSymbolAddress((void**)&cw,     g_cw);
    cudaGetSymbolAddress((void**)&dinv,   g_dinv);
    cudaGetSymbolAddress((void**)&h1,     g_h1);
    cudaGetSymbolAddress((void**)&out1,   g_out1);
    cudaGetSymbolAddress((void**)&h2,     g_h2);

    // 0) histogram by dst (straight from raw edge buffer)
    zero_hist<<<(NN + 255) / 256, 256>>>(hist, NN);
    detect_dtype<<<1, 32>>>((const unsigned int*)ei, in_sizes[1], is64);
    hist_k<<<(E + 255) / 256, 256>>>(ei, E, is64, hist);

    // 1) normalization + CSR offsets + fill
    dinv_k<<<(NN + 255) / 256, 256>>>(hist, dinv, NN);
    scan_reduce<<<NB, 256>>>(hist, bsum, NN);
    scan_bsums<<<1, 128>>>(bsum, NB);
    scan_final<<<NB, 256>>>(hist, bsum, offs, cursor, NN);
    set_last<<<1, 1>>>(offs, NN, E);
    fill_csr<<<(E + 255) / 256, 256>>>(ei, E, is64, dinv, cursor, csrc, cw);

    // 2) layer 1
    dim3 g1((NN + 127) / 128, F1 / 64);
    gemm_dual<false><<<g1, 128>>>(x, W1, h1, out1, dinv, b1, NN, KDIM, F1);
    aggregate128<<<(NN * 32 + 255) / 256, 256>>>(offs, csrc, cw, h1, out1, NN);

    // 3) layer 2 (ReLU on input fused into A-load; epilogue pre-seeds d_out)
    dim3 g2((NN + 127) / 128, F2 / 64);
    gemm_dual<true><<<g2, 128>>>(out1, W2, h2, out, dinv, b2, NN, KDIM, F2);
    aggregate64_relu<<<(NN * 32 + 255) / 256, 256>>>(offs, csrc, cw, h2, out, NN);
}

// round 7
// speedup vs baseline: 1.9169x; 1.2930x over previous
#include <cuda_runtime.h>
#include <cuda_fp16.h>

#define NN   100000
#define F1   128
#define F2   64
#define KD   128
#define EMAX 1700000

// ---------------- scratch (device globals; no allocation allowed) ----------------
__device__ int    g_is64;
__device__ int    g_hist[NN];
__device__ int    g_offs[NN + 1];
__device__ int    g_cursor[NN];
__device__ int    g_blocksum[128];
__device__ int    g_csrc[EMAX];
__device__ float  g_cw[EMAX];
__device__ float  g_dinv[NN];
__device__ __half g_h1[(size_t)NN * F1];    // layer-1 messages (fp16)
__device__ float  g_out1[(size_t)NN * F1];  // layer-1 pre-seed + aggregation (fp32)
__device__ __half g_a16[(size_t)NN * F1];   // relu(layer-1 out) fp16 = layer-2 GEMM A
__device__ __half g_h2[(size_t)NN * F2];    // layer-2 messages (fp16)

// ---------------- edge-index dtype sniff ----------------
__global__ void detect_dtype(const unsigned int* __restrict__ raw, int nelem, int* flag) {
    if (threadIdx.x == 0 && blockIdx.x == 0) {
        int half = nelem >> 1;
        int step = half / 64; if (step < 1) step = 1;
        unsigned int acc = 0;
        for (int i = 0; i < 64; i++) {
            int k = (int)(((long long)i * step) % half);
            acc |= raw[2 * k + 1];
        }
        *flag = (acc == 0) ? 1 : 0;
    }
}

__global__ void zero_hist(int* __restrict__ h, int n) {
    int i = blockIdx.x * blockDim.x + threadIdx.x;
    if (i < n) h[i] = 0;
}

__global__ void hist_k(const void* __restrict__ raw, int E,
                       const int* __restrict__ flag, int* __restrict__ hist) {
    int e = blockIdx.x * blockDim.x + threadIdx.x;
    if (e >= E) return;
    int d;
    if (*flag) d = (int)((const long long*)raw)[(size_t)E + e];
    else       d = ((const int*)raw)[E + e];
    atomicAdd(&hist[d], 1);
}

__global__ void dinv_k(const int* __restrict__ hist, float* __restrict__ dinv, int n) {
    int i = blockIdx.x * blockDim.x + threadIdx.x;
    if (i < n) dinv[i] = rsqrtf(1.0f + (float)hist[i]);
}

// ---------------- exclusive scan over NN bins ----------------
__global__ void scan_reduce(const int* __restrict__ hist, int* __restrict__ bsum, int n) {
    __shared__ int sh[256];
    int base = blockIdx.x * 1024, t = threadIdx.x;
    int s = 0;
    #pragma unroll
    for (int j = 0; j < 4; j++) {
        int idx = base + t * 4 + j;
        s += (idx < n) ? hist[idx] : 0;
    }
    sh[t] = s; __syncthreads();
    for (int off = 128; off > 0; off >>= 1) {
        if (t < off) sh[t] += sh[t + off];
        __syncthreads();
    }
    if (t == 0) bsum[blockIdx.x] = sh[0];
}

__global__ void scan_bsums(int* __restrict__ bsum, int nb) {
    __shared__ int sh[128];
    int t = threadIdx.x;
    int own = (t < nb) ? bsum[t] : 0;
    sh[t] = own; __syncthreads();
    for (int off = 1; off < 128; off <<= 1) {
        int y = (t >= off) ? sh[t - off] : 0;
        __syncthreads();
        sh[t] += y;
        __syncthreads();
    }
    if (t < nb) bsum[t] = sh[t] - own;
}

__global__ void scan_final(const int* __restrict__ hist, const int* __restrict__ bbase,
                           int* __restrict__ offs, int* __restrict__ cursor, int n) {
    __shared__ int sh[256];
    int base = blockIdx.x * 1024, t = threadIdx.x;
    int i0 = base + t * 4;
    int v[4], s = 0;
    #pragma unroll
    for (int j = 0; j < 4; j++) {
        int idx = i0 + j;
        v[j] = (idx < n) ? hist[idx] : 0;
        s += v[j];
    }
    sh[t] = s; __syncthreads();
    for (int off = 1; off < 256; off <<= 1) {
        int y = (t >= off) ? sh[t - off] : 0;
        __syncthreads();
        sh[t] += y;
        __syncthreads();
    }
    int run = bbase[blockIdx.x] + sh[t] - s;
    #pragma unroll
    for (int j = 0; j < 4; j++) {
        int idx = i0 + j;
        if (idx < n) { offs[idx] = run; cursor[idx] = run; run += v[j]; }
    }
}

__global__ void set_last(int* __restrict__ offs, int n, int E) {
    if (threadIdx.x == 0) offs[n] = E;
}

__global__ void fill_csr(const void* __restrict__ raw, int E,
                         const int* __restrict__ flag,
                         const float* __restrict__ dinv, int* __restrict__ cursor,
                         int* __restrict__ csrc, float* __restrict__ cw) {
    int e = blockIdx.x * blockDim.x + threadIdx.x;
    if (e >= E) return;
    int s, d;
    if (*flag) {
        const long long* p = (const long long*)raw;
        s = (int)p[e]; d = (int)p[(size_t)E + e];
    } else {
        const int* p = (const int*)raw;
        s = p[e]; d = p[E + e];
    }
    int pos = atomicAdd(&cursor[d], 1);
    csrc[pos] = s;
    cw[pos]   = __ldg(dinv + s) * __ldg(dinv + d);
}

// ---------------- tensor-core GEMM (HMMA m16n8k16), dual epilogue ----------------
// Block: 256 thr = 8 warps (4 along M x 2 along N). Tile M=128, N=64, full K.
// B (fp32 weights) -> smem transposed [n][k] fp16, pad 8 (conflict-free b-frag LDS.32).
// A: direct global loads; AHALF=0 -> fp32 (float2->half2 cvt), AHALF=1 -> fp16.
// Epilogue: H = fp16(acc); OUT = acc*dinv[row]^2 + bias (fp32 pre-seed).
template <bool AHALF>
__global__ __launch_bounds__(256)
void gemm_mma(const void* __restrict__ Aptr, const float* __restrict__ B,
              __half* __restrict__ H, float* __restrict__ OUT,
              const float* __restrict__ dinv, const float* __restrict__ bias,
              int N, int F)
{
    __shared__ __align__(16) __half Bs[64][KD + 8];

    const int t    = threadIdx.x;
    const int bm0  = blockIdx.x * 128;
    const int bn0  = blockIdx.y * 64;

    // load B slice [KD][64] -> Bs[n][k] fp16
    for (int idx = t; idx < 64 * KD; idx += 256) {
        int n = idx & 63, k = idx >> 6;
        Bs[n][k] = __float2half_rn(B[(size_t)k * F + bn0 + n]);
    }
    __syncthreads();

    const int lane = t & 31, warp = t >> 5;
    const int wm = warp & 3, wn = warp >> 2;
    const int gid = lane >> 2, q = lane & 3;
    const int r0 = bm0 + wm * 32 + gid;     // + mt*16, +8 for second row group

    float c[2][4][4] = {};

    #pragma unroll
    for (int ks = 0; ks < KD / 16; ks++) {
        const int k0 = ks * 16;
        unsigned int a[2][4];
        #pragma unroll
        for (int mt = 0; mt < 2; mt++) {
            int ra = r0 + mt * 16; if (ra > N - 1) ra = N - 1;
            int rb = r0 + mt * 16 + 8; if (rb > N - 1) rb = N - 1;
            if (AHALF) {
                const __half* A16 = (const __half*)Aptr;
                a[mt][0] = *(const unsigned int*)(A16 + (size_t)ra * KD + k0 + 2 * q);
                a[mt][1] = *(const unsigned int*)(A16 + (size_t)rb * KD + k0 + 2 * q);
                a[mt][2] = *(const unsigned int*)(A16 + (size_t)ra * KD + k0 + 2 * q + 8);
                a[mt][3] = *(const unsigned int*)(A16 + (size_t)rb * KD + k0 + 2 * q + 8);
            } else {
                const float* A32 = (const float*)Aptr;
                float2 va = *(const float2*)(A32 + (size_t)ra * KD + k0 + 2 * q);
                float2 vb = *(const float2*)(A32 + (size_t)rb * KD + k0 + 2 * q);
                float2 vc = *(const float2*)(A32 + (size_t)ra * KD + k0 + 2 * q + 8);
                float2 vd = *(const float2*)(A32 + (size_t)rb * KD + k0 + 2 * q + 8);
                __half2 ha = __float22half2_rn(va), hb = __float22half2_rn(vb);
                __half2 hc = __float22half2_rn(vc), hd = __float22half2_rn(vd);
                a[mt][0] = *(const unsigned int*)&ha;
                a[mt][1] = *(const unsigned int*)&hb;
                a[mt][2] = *(const unsigned int*)&hc;
                a[mt][3] = *(const unsigned int*)&hd;
            }
        }
        unsigned int b[4][2];
        #pragma unroll
        for (int nt = 0; nt < 4; nt++) {
            const unsigned int* brow =
                (const unsigned int*)&Bs[wn * 32 + nt * 8 + gid][0];
            b[nt][0] = brow[(k0 >> 1) + q];
            b[nt][1] = brow[(k0 >> 1) + q + 4];
        }
        #pragma unroll
        for (int mt = 0; mt < 2; mt++)
            #pragma unroll
            for (int nt = 0; nt < 4; nt++) {
                asm volatile(
                    "mma.sync.aligned.m16n8k16.row.col.f32.f16.f16.f32 "
                    "{%0,%1,%2,%3}, {%4,%5,%6,%7}, {%8,%9}, {%0,%1,%2,%3};"
                    : "+f"(c[mt][nt][0]), "+f"(c[mt][nt][1]),
                      "+f"(c[mt][nt][2]), "+f"(c[mt][nt][3])
                    : "r"(a[mt][0]), "r"(a[mt][1]), "r"(a[mt][2]), "r"(a[mt][3]),
                      "r"(b[nt][0]), "r"(b[nt][1]));
            }
    }

    // epilogue
    #pragma unroll
    for (int mt = 0; mt < 2; mt++) {
        int ra = r0 + mt * 16;
        int rb = ra + 8;
        float da2 = 0.f, db2 = 0.f;
        if (ra < N) { float d = dinv[ra]; da2 = d * d; }
        if (rb < N) { float d = dinv[rb]; db2 = d * d; }
        #pragma unroll
        for (int nt = 0; nt < 4; nt++) {
            int col = bn0 + wn * 32 + nt * 8 + 2 * q;
            float2 bb = *(const float2*)(bias + col);
            if (ra < N) {
                size_t base = (size_t)ra * F + col;
                __half2 hh = __float22half2_rn(make_float2(c[mt][nt][0], c[mt][nt][1]));
                *(unsigned int*)(H + base) = *(const unsigned int*)&hh;
                *(float2*)(OUT + base) =
                    make_float2(c[mt][nt][0] * da2 + bb.x, c[mt][nt][1] * da2 + bb.y);
            }
            if (rb < N) {
                size_t base = (size_t)rb * F + col;
                __half2 hh = __float22half2_rn(make_float2(c[mt][nt][2], c[mt][nt][3]));
                *(unsigned int*)(H + base) = *(const unsigned int*)&hh;
                *(float2*)(OUT + base) =
                    make_float2(c[mt][nt][2] * db2 + bb.x, c[mt][nt][3] * db2 + bb.y);
            }
        }
    }
}

// ---------------- CSR aggregation layer 1: fp16 gather, fp32 acc -> relu fp16 ----------------
// Warp per node, F=128: lane owns 4 halves. Reads fp32 pre-seed, writes relu'd fp16 a16.
__global__ __launch_bounds__(256)
void aggregate128(const int* __restrict__ offs, const int* __restrict__ csrc,
                  const float* __restrict__ cw, const __half* __restrict__ H,
                  const float* __restrict__ PRE, __half* __restrict__ A16, int n)
{
    int warp = (blockIdx.x * blockDim.x + threadIdx.x) >> 5;
    int lane = threadIdx.x & 31;
    if (warp >= n) return;
    int beg = __ldg(offs + warp), end = __ldg(offs + warp + 1);

    const uint2* Hv = reinterpret_cast<const uint2*>(H);
    float4 acc = *(reinterpret_cast<const float4*>(PRE + (size_t)warp * 128) + lane);

    int j = beg;
    for (; j + 1 < end; j += 2) {
        int   s0 = __ldg(csrc + j);     float w0 = __ldg(cw + j);
        int   s1 = __ldg(csrc + j + 1); float w1 = __ldg(cw + j + 1);
        uint2 u0 = __ldg(Hv + (size_t)s0 * 32 + lane);
        uint2 u1 = __ldg(Hv + (size_t)s1 * 32 + lane);
        float2 a0 = __half22float2(*reinterpret_cast<const __half2*>(&u0.x));
        float2 b0 = __half22float2(*reinterpret_cast<const __half2*>(&u0.y));
        float2 a1 = __half22float2(*reinterpret_cast<const __half2*>(&u1.x));
        float2 b1 = __half22float2(*reinterpret_cast<const __half2*>(&u1.y));
        acc.x += a0.x * w0 + a1.x * w1;
        acc.y += a0.y * w0 + a1.y * w1;
        acc.z += b0.x * w0 + b1.x * w1;
        acc.w += b0.y * w0 + b1.y * w1;
    }
    if (j < end) {
        int s = __ldg(csrc + j); float w = __ldg(cw + j);
        uint2 u = __ldg(Hv + (size_t)s * 32 + lane);
        float2 a = __half22float2(*reinterpret_cast<const __half2*>(&u.x));
        float2 b = __half22float2(*reinterpret_cast<const __half2*>(&u.y));
        acc.x += a.x * w; acc.y += a.y * w; acc.z += b.x * w; acc.w += b.y * w;
    }
    __half2 h0 = __float22half2_rn(make_float2(fmaxf(acc.x, 0.f), fmaxf(acc.y, 0.f)));
    __half2 h1 = __float22half2_rn(make_float2(fmaxf(acc.z, 0.f), fmaxf(acc.w, 0.f)));
    uint2 pk = make_uint2(*(const unsigned int*)&h0, *(const unsigned int*)&h1);
    *(reinterpret_cast<uint2*>(A16 + (size_t)warp * 128) + lane) = pk;
}

// ---------------- CSR aggregation layer 2: fp16 gather -> relu fp32 (d_out) ----------------
__global__ __launch_bounds__(256)
void aggregate64_relu(const int* __restrict__ offs, const int* __restrict__ csrc,
                      const float* __restrict__ cw, const __half* __restrict__ H,
                      float* __restrict__ OUT, int n)
{
    int warp = (blockIdx.x * blockDim.x + threadIdx.x) >> 5;
    int lane = threadIdx.x & 31;
    if (warp >= n) return;
    int beg = __ldg(offs + warp), end = __ldg(offs + warp + 1);

    const unsigned int* Hv = reinterpret_cast<const unsigned int*>(H);
    float2* op = reinterpret_cast<float2*>(OUT + (size_t)warp * 64) + lane;
    float2 acc = *op;

    int j = beg;
    for (; j + 1 < end; j += 2) {
        int   s0 = __ldg(csrc + j);     float w0 = __ldg(cw + j);
        int   s1 = __ldg(csrc + j + 1); float w1 = __ldg(cw + j + 1);
        unsigned int u0 = __ldg(Hv + (size_t)s0 * 32 + lane);
        unsigned int u1 = __ldg(Hv + (size_t)s1 * 32 + lane);
        float2 v0 = __half22float2(*reinterpret_cast<const __half2*>(&u0));
        float2 v1 = __half22float2(*reinterpret_cast<const __half2*>(&u1));
        acc.x += v0.x * w0 + v1.x * w1;
        acc.y += v0.y * w0 + v1.y * w1;
    }
    if (j < end) {
        int s = __ldg(csrc + j); float w = __ldg(cw + j);
        unsigned int u = __ldg(Hv + (size_t)s * 32 + lane);
        float2 v = __half22float2(*reinterpret_cast<const __half2*>(&u));
        acc.x += v.x * w; acc.y += v.y * w;
    }
    acc.x = fmaxf(acc.x, 0.f);
    acc.y = fmaxf(acc.y, 0.f);
    *op = acc;
}

// ---------------- launch ----------------
extern "C" void kernel_launch(void* const* d_in, const int* in_sizes, int n_in,
                              void* d_out, int out_size)
{
    const float* x   = (const float*)d_in[0];
    const void*  ei  = d_in[1];
    const float* W1  = (const float*)d_in[2];
    const float* b1  = (const float*)d_in[3];
    const float* W2  = (const float*)d_in[4];
    const float* b2  = (const float*)d_in[5];
    float*       out = (float*)d_out;

    const int E  = in_sizes[1] / 2;
    const int NB = (NN + 1023) / 1024;

    int *is64, *hist, *offs, *cursor, *bsum, *csrc;
    float *cw, *dinv, *out1;
    __half *h1, *h2, *a16;
    cudaGetSymbolAddress((void**)&is64,   g_is64);
    cudaGetSymbolAddress((void**)&hist,   g_hist);
    cudaGetSymbolAddress((void**)&offs,   g_offs);
    cudaGetSymbolAddress((void**)&cursor, g_cursor);
    cudaGetSymbolAddress((void**)&bsum,   g_blocksum);
    cudaGetSymbolAddress((void**)&csrc,   g_csrc);
    cudaGetSymbolAddress((void**)&cw,     g_cw);
    cudaGetSymbolAddress((void**)&dinv,   g_dinv);
    cudaGetSymbolAddress((void**)&h1,     g_h1);
    cudaGetSymbolAddress((void**)&out1,   g_out1);
    cudaGetSymbolAddress((void**)&a16,    g_a16);
    cudaGetSymbolAddress((void**)&h2,     g_h2);

    // 0) histogram by dst
    zero_hist<<<(NN + 255) / 256, 256>>>(hist, NN);
    detect_dtype<<<1, 32>>>((const unsigned int*)ei, in_sizes[1], is64);
    hist_k<<<(E + 255) / 256, 256>>>(ei, E, is64, hist);

    // 1) normalization + CSR
    dinv_k<<<(NN + 255) / 256, 256>>>(hist, dinv, NN);
    scan_reduce<<<NB, 256>>>(hist, bsum, NN);
    scan_bsums<<<1, 128>>>(bsum, NB);
    scan_final<<<NB, 256>>>(hist, bsum, offs, cursor, NN);
    set_last<<<1, 1>>>(offs, NN, E);
    fill_csr<<<(E + 255) / 256, 256>>>(ei, E, is64, dinv, cursor, csrc, cw);

    // 2) layer 1: HMMA GEMM (fp32 A cvt in-reg), then aggregate -> relu fp16 a16
    dim3 g1((NN + 127) / 128, F1 / 64);
    gemm_mma<false><<<g1, 256>>>(x, W1, h1, out1, dinv, b1, NN, F1);
    aggregate128<<<(NN * 32 + 255) / 256, 256>>>(offs, csrc, cw, h1, out1, a16, NN);

    // 3) layer 2: HMMA GEMM (fp16 A = a16), aggregate + relu into d_out
    dim3 g2((NN + 127) / 128, F2 / 64);
    gemm_mma<true><<<g2, 256>>>(a16, W2, h2, out, dinv, b2, NN, F2);
    aggregate64_relu<<<(NN * 32 + 255) / 256, 256>>>(offs, csrc, cw, h2, out, NN);
}